// round 1
// baseline (speedup 1.0000x reference)
#include <cuda_runtime.h>
#include <math.h>
#include <stdint.h>

#define NG   256
#define NG2  (NG*NG)
#define NG3  (NG*NG*NG)

// ---- device scratch (static allocation is the sanctioned mechanism) ----
static __device__ uint8_t g_prot[NG3];   // d < vr for some atom
static __device__ uint8_t g_occ [NG3];   // d < vr + 1.1 for some atom (protein|bound)
static __device__ uint8_t g_solv[NG3];   // final solvent bool
static __device__ float   g_fA  [NG3];
static __device__ float   g_fB  [NG3];

// erosion offsets: all (i,j,k) != 0 with i^2+j^2+k^2 <= 5  (|o|*SPACING <= 0.9)
// sorted by norm^2 ascending for early-exit scanning
__device__ const int EOx[56] = {
  1,-1,0,0,0,0,
  1,1,-1,-1,1,1,-1,-1,0,0,0,0,
  1,1,1,1,-1,-1,-1,-1,
  2,-2,0,0,0,0,
  2,2,-2,-2,2,2,-2,-2,1,-1,1,-1,0,0,0,0,1,-1,1,-1,0,0,0,0
};
__device__ const int EOy[56] = {
  0,0,1,-1,0,0,
  1,-1,1,-1,0,0,0,0,1,1,-1,-1,
  1,1,-1,-1,1,1,-1,-1,
  0,0,2,-2,0,0,
  1,-1,1,-1,0,0,0,0,2,2,-2,-2,2,2,-2,-2,0,0,0,0,1,-1,1,-1
};
__device__ const int EOz[56] = {
  0,0,0,0,1,-1,
  0,0,0,0,1,-1,1,-1,1,-1,1,-1,
  1,-1,1,-1,1,-1,1,-1,
  0,0,0,0,2,-2,
  0,0,0,0,1,-1,1,-1,0,0,0,0,1,-1,1,-1,2,2,-2,-2,2,2,-2,-2
};

// ---- zero the two splat masks (33.5 MB) ----
__global__ void zero_kernel() {
    unsigned i = blockIdx.x * blockDim.x + threadIdx.x;
    const uint4 z = make_uint4(0u, 0u, 0u, 0u);
    const unsigned words = NG3 / 16;        // uint4 words per array
    if (i < words)             reinterpret_cast<uint4*>(g_prot)[i]         = z;
    else if (i < 2u * words)   reinterpret_cast<uint4*>(g_occ )[i - words] = z;
}

// ---- splat: one block per atom, threads over the 17x17 (dx,dy) pairs ----
__global__ void splat_kernel(const float* __restrict__ xyz,
                             const float* __restrict__ vdw,
                             int n_atoms) {
    const float SP = 0.390625f;              // 100/256, exact in f32
    int a = blockIdx.x;
    if (a >= n_atoms) return;
    float ax = xyz[3*a + 0];
    float ay = xyz[3*a + 1];
    float az = xyz[3*a + 2];
    float vr = vdw[a];

    // base = floor(xyz / SPACING): IEEE divide to match the reference exactly
    int bx = (int)floorf(__fdiv_rn(ax, SP));
    int by = (int)floorf(__fdiv_rn(ay, SP));
    int bz = (int)floorf(__fdiv_rn(az, SP));

    float R  = vr + 1.1f;                    // reference compares d < vr + SOLVENT_R (f32)
    float R2 = R * R * 1.00002f + 1e-4f;     // padded, only used for range culling

    for (int p = threadIdx.x; p < 289; p += blockDim.x) {
        int dx = p / 17 - 8;
        int dy = p % 17 - 8;
        float rx = (float)(bx + dx) * SP - ax;
        float ry = (float)(by + dy) * SP - ay;
        float rxy2 = rx * rx + ry * ry;
        if (rxy2 > R2) continue;             // whole z-row outside shell

        float half = __fsqrt_rn(R2 - rxy2);
        int zlo = (int)floorf((az - half) * 2.56f) - 1;   // padded range; exact
        int zhi = (int)ceilf ((az + half) * 2.56f) + 1;   // predicate still checked per cell
        zlo = max(zlo, bz - 8);
        zhi = min(zhi, bz + 8);              // reference window is truncated to +-8

        int rowbase = (((((bx + dx) & 255) << 8) | ((by + dy) & 255)) << 8);
        for (int zc = zlo; zc <= zhi; ++zc) {
            float rz = (float)zc * SP - az;
            float d  = __fsqrt_rn(rx * rx + ry * ry + rz * rz);
            if (d < R) {
                int idx = rowbase | (zc & 255);
                g_occ[idx] = 1;              // race-free: everyone stores 1
                if (d < vr) g_prot[idx] = 1;
            }
        }
    }
}

// ---- classify + erosion flip ----
// solvent = def_solv | (boundary & exists def_solv neighbor within 0.9 A)
__global__ void classify_kernel() {
    int i = blockIdx.x * blockDim.x + threadIdx.x;
    if (i >= NG3) return;
    unsigned o = g_occ[i];
    unsigned res;
    if (!o) {
        res = 1u;                            // default solvent
    } else if (g_prot[i]) {
        res = 0u;                            // protein stays protein
    } else {
        // boundary cell: flip to solvent if any def_solv neighbor in erosion ball
        int x = i >> 16, y = (i >> 8) & 255, z = i & 255;
        res = 0u;
        #pragma unroll 1
        for (int k = 0; k < 56; ++k) {
            int ni = (((((x + EOx[k]) & 255) << 8) | ((y + EOy[k]) & 255)) << 8)
                     | ((z + EOz[k]) & 255);
            if (!g_occ[ni]) { res = 1u; break; }
        }
    }
    g_solv[i] = (uint8_t)res;
}

// ---- separable periodic 3-tap Gaussian, three passes ----
__global__ void blur_z_kernel(float a0, float a1) {
    int i = blockIdx.x * blockDim.x + threadIdx.x;
    if (i >= NG3) return;
    int z  = i & 255;
    int im = (z == 0)   ? i + 255 : i - 1;
    int ip = (z == 255) ? i - 255 : i + 1;
    g_fA[i] = a1 * ((float)g_solv[im] + (float)g_solv[ip]) + a0 * (float)g_solv[i];
}

__global__ void blur_y_kernel(float a0, float a1) {
    int i = blockIdx.x * blockDim.x + threadIdx.x;
    if (i >= NG3) return;
    int y  = (i >> 8) & 255;
    int im = (y == 0)   ? i + 255 * NG : i - NG;
    int ip = (y == 255) ? i - 255 * NG : i + NG;
    g_fB[i] = a1 * (g_fA[im] + g_fA[ip]) + a0 * g_fA[i];
}

__global__ void blur_x_kernel(float* __restrict__ out, float a0, float a1) {
    int i = blockIdx.x * blockDim.x + threadIdx.x;
    if (i >= NG3) return;
    int x  = i >> 16;
    int im = (x == 0)   ? i + 255 * NG2 : i - NG2;
    int ip = (x == 255) ? i - 255 * NG2 : i + NG2;
    out[i] = a1 * (g_fB[im] + g_fB[ip]) + a0 * g_fB[i];
}

extern "C" void kernel_launch(void* const* d_in, const int* in_sizes, int n_in,
                              void* d_out, int out_size) {
    const float* xyz = (const float*)d_in[0];   // (N_ATOMS, 3) f32
    const float* vdw = (const float*)d_in[1];   // (N_ATOMS,)  f32
    int n_atoms = in_sizes[1];
    float* out = (float*)d_out;

    // Gaussian weights computed in double to match numpy's float64 kernel build,
    // then cast to f32 (reference casts k3 to f32 before the conv).
    double sigma = 1.1 / (100.0 / 256.0) / 4.0;   // 0.704
    double w  = exp(-1.0 / (2.0 * sigma * sigma));
    double s  = 1.0 + 2.0 * w;
    float a0 = (float)(1.0 / w / s * w);          // = 1/s
    float a1 = (float)(w / s);
    a0 = (float)(1.0 / s);

    const int T = 256;
    zero_kernel    <<<(2 * (NG3 / 16) + T - 1) / T, T>>>();
    splat_kernel   <<<n_atoms, 128>>>(xyz, vdw, n_atoms);
    classify_kernel<<<NG3 / T, T>>>();
    blur_z_kernel  <<<NG3 / T, T>>>(a0, a1);
    blur_y_kernel  <<<NG3 / T, T>>>(a0, a1);
    blur_x_kernel  <<<NG3 / T, T>>>(out, a0, a1);
}

// round 2
// speedup vs baseline: 7.8712x; 7.8712x over previous
#include <cuda_runtime.h>
#include <math.h>
#include <stdint.h>

#define NG   256
#define NG2  65536
#define NG3  16777216
#define NW   (NG3/32)          // 524288 bit-words per mask
#define SP   0.390625f          // 100/256, exact in f32

// ---- device scratch (bit masks: word = zw*65536 + x*256 + y) ----
static __device__ uint32_t g_occb [NW];
static __device__ uint32_t g_protb[NW];
static __device__ uint32_t g_solvb[NW];
static __device__ float    g_fA[NG3];
static __device__ float    g_fB[NG3];

// ---- zero the two splat bitmasks (4 MB) ----
__global__ void zero_kernel() {
    unsigned i = blockIdx.x * blockDim.x + threadIdx.x;
    const uint4 z = make_uint4(0u, 0u, 0u, 0u);
    if (i < NW / 4)          reinterpret_cast<uint4*>(g_occb )[i]          = z;
    else if (i < NW / 2)     reinterpret_cast<uint4*>(g_protb)[i - NW / 4] = z;
}

// smallest float T such that sqrt_rn(T) >= R  =>  (s < T) <=> (sqrt_rn(s) < R)
__device__ __forceinline__ float cut_threshold(float R) {
    float t = __fmul_rn(R, R);
    while (__fsqrt_rn(t) >= R)
        t = __uint_as_float(__float_as_uint(t) - 1u);
    while (__fsqrt_rn(__uint_as_float(__float_as_uint(t) + 1u)) < R)
        t = __uint_as_float(__float_as_uint(t) + 1u);
    return __uint_as_float(__float_as_uint(t) + 1u);
}

// ---- splat: one block per atom, bit stores via atomicOr ----
__global__ void splat_kernel(const float* __restrict__ xyz,
                             const float* __restrict__ vdw,
                             int n_atoms) {
    int a = blockIdx.x;
    if (a >= n_atoms) return;
    float ax = xyz[3*a], ay = xyz[3*a+1], az = xyz[3*a+2];
    float vr = vdw[a];
    float R  = __fadd_rn(vr, 1.1f);
    float Tocc = cut_threshold(R);     // exact squared-threshold for d < vr+1.1
    float Tpro = cut_threshold(vr);    // exact squared-threshold for d < vr

    int bx = (int)floorf(__fdiv_rn(ax, SP));
    int by = (int)floorf(__fdiv_rn(ay, SP));
    int bz = (int)floorf(__fdiv_rn(az, SP));

    for (int p = threadIdx.x; p < 289; p += blockDim.x) {
        int dx = p / 17 - 8;
        int dy = p % 17 - 8;
        int cx = bx + dx, cy = by + dy;
        float rx = __fsub_rn(__fmul_rn((float)cx, SP), ax);
        float ry = __fsub_rn(__fmul_rn((float)cy, SP), ay);
        float rxy2 = __fadd_rn(__fmul_rn(rx, rx), __fmul_rn(ry, ry));
        if (rxy2 >= Tocc) continue;                    // exact cull (s >= rxy2)

        float h = sqrtf((Tocc - rxy2) * 1.0002f + 1e-6f);   // padded range cull only
        int zlo = (int)floorf((az - h) * 2.56f) - 1;
        int zhi = (int)ceilf ((az + h) * 2.56f) + 1;
        zlo = max(zlo, bz - 8);
        zhi = min(zhi, bz + 8);                        // reference window truncation

        // accumulate bits; a <=17-cell run touches at most 2 distinct words
        uint32_t wi0 = 0xffffffffu, wi1 = 0xffffffffu;
        uint32_t mo0 = 0, mo1 = 0, mp0 = 0, mp1 = 0;
        for (int zc = zlo; zc <= zhi; ++zc) {
            float rz = __fsub_rn(__fmul_rn((float)zc, SP), az);
            float s  = __fadd_rn(rxy2, __fmul_rn(rz, rz));  // exact ref sum order
            if (s < Tocc) {
                int zp = zc & 255;
                uint32_t w = (uint32_t)(zp >> 5);
                uint32_t b = 1u << (zp & 31);
                bool pr = (s < Tpro);
                if (wi0 == 0xffffffffu || w == wi0) {
                    wi0 = w; mo0 |= b; if (pr) mp0 |= b;
                } else {
                    wi1 = w; mo1 |= b; if (pr) mp1 |= b;
                }
            }
        }
        int colbase = ((cx & 255) << 8) | (cy & 255);
        if (mo0) atomicOr(&g_occb [(wi0 << 16) + colbase], mo0);
        if (mp0) atomicOr(&g_protb[(wi0 << 16) + colbase], mp0);
        if (mo1) atomicOr(&g_occb [(wi1 << 16) + colbase], mo1);
        if (mp1) atomicOr(&g_protb[(wi1 << 16) + colbase], mp1);
    }
}

// ---- classify: bitwise erosion/flip. solv = ds | (nb & ~prot) ----
// nb = OR of z-dilated def_solv over the 21 (dx,dy) columns of the <=sqrt(5) ball.
__global__ void classify_kernel() {
    __shared__ uint32_t sD0[8 * 400];   // def_solv
    __shared__ uint32_t sD1[8 * 400];   // dilated +-1 in z
    __shared__ uint32_t sD2[8 * 400];   // dilated +-2 in z
    int bx0 = (blockIdx.x & 15) * 16;
    int by0 = (blockIdx.x >> 4) * 16;
    int t = threadIdx.x;

    for (int c = t; c < 400; c += 256) {
        int lx = c % 20, ly = c / 20;
        int gx = (bx0 + lx - 2) & 255;
        int gy = (by0 + ly - 2) & 255;
        int col = (gx << 8) | gy;
        uint32_t ds[8], d1[8], d2[8];
        #pragma unroll
        for (int i = 0; i < 8; i++) ds[i] = ~g_occb[(i << 16) + col];
        #pragma unroll
        for (int i = 0; i < 8; i++)
            d1[i] = ds[i] | (ds[i] << 1) | (ds[(i+7)&7] >> 31)
                          | (ds[i] >> 1) | (ds[(i+1)&7] << 31);
        #pragma unroll
        for (int i = 0; i < 8; i++)
            d2[i] = d1[i] | (d1[i] << 1) | (d1[(i+7)&7] >> 31)
                          | (d1[i] >> 1) | (d1[(i+1)&7] << 31);
        #pragma unroll
        for (int i = 0; i < 8; i++) {
            sD0[i*400 + c] = ds[i];
            sD1[i*400 + c] = d1[i];
            sD2[i*400 + c] = d2[i];
        }
    }
    __syncthreads();

    int lx = (t & 15) + 2, ly = (t >> 4) + 2;
    int gx = (bx0 + lx - 2) & 255;
    int gy = (by0 + ly - 2) & 255;
    int col = (gx << 8) | gy;
    int cc = ly * 20 + lx;
    #pragma unroll
    for (int i = 0; i < 8; i++) {
        const uint32_t* D0 = sD0 + i * 400;
        const uint32_t* D1 = sD1 + i * 400;
        const uint32_t* D2 = sD2 + i * 400;
        uint32_t nb =
            D2[cc] | D2[cc+1]  | D2[cc-1]  | D2[cc+20] | D2[cc-20] |
            D1[cc+21] | D1[cc+19] | D1[cc-19] | D1[cc-21] |
            D1[cc+2]  | D1[cc-2]  | D1[cc+40] | D1[cc-40] |
            D0[cc+22] | D0[cc+18] | D0[cc-18] | D0[cc-22] |
            D0[cc+41] | D0[cc+39] | D0[cc-39] | D0[cc-41];
        uint32_t p = g_protb[(i << 16) + col];
        g_solvb[(i << 16) + col] = D0[cc] | (nb & ~p);
    }
}

// ---- blur z: bits -> f32 via 6-bit -> float4 LUT ----
__global__ void blur_z_kernel(float a0, float a1) {
    __shared__ float4 lut[64];
    int t = threadIdx.x;
    if (t < 64) {
        float b0 = (float)( t       & 1), b1 = (float)((t >> 1) & 1);
        float b2 = (float)((t >> 2) & 1), b3 = (float)((t >> 3) & 1);
        float b4 = (float)((t >> 4) & 1), b5 = (float)((t >> 5) & 1);
        lut[t] = make_float4(a1*b0 + a0*b1 + a1*b2,
                             a1*b1 + a0*b2 + a1*b3,
                             a1*b2 + a0*b3 + a1*b4,
                             a1*b3 + a0*b4 + a1*b5);
    }
    __syncthreads();
    int gt  = blockIdx.x * 256 + t;        // 4,194,304 threads, 4 z-cells each
    int col = gt >> 6;                     // warp covers half a column -> coalesced
    int z   = (gt & 63) << 2;
    int zm  = (z - 1) & 255;
    int wA  = zm >> 5;
    uint32_t lo = g_solvb[( wA          << 16) + col];
    uint32_t hi = g_solvb[(((wA+1) & 7) << 16) + col];
    uint32_t idx = __funnelshift_r(lo, hi, zm & 31) & 63;
    reinterpret_cast<float4*>(g_fA)[(col << 6) + (z >> 2)] = lut[idx];
}

// ---- blur y ----
__global__ void blur_y_kernel(float a0, float a1) {
    int gt = blockIdx.x * 256 + threadIdx.x;
    int y  = (gt >> 6) & 255;
    const float4* A = reinterpret_cast<const float4*>(g_fA);
    float4 c = A[gt];
    float4 m = A[(y == 0)   ? gt + 255*64 : gt - 64];
    float4 p = A[(y == 255) ? gt - 255*64 : gt + 64];
    float4 o;
    o.x = fmaf(a1, m.x + p.x, a0 * c.x);
    o.y = fmaf(a1, m.y + p.y, a0 * c.y);
    o.z = fmaf(a1, m.z + p.z, a0 * c.z);
    o.w = fmaf(a1, m.w + p.w, a0 * c.w);
    reinterpret_cast<float4*>(g_fB)[gt] = o;
}

// ---- blur x (writes final output) ----
__global__ void blur_x_kernel(float* __restrict__ out, float a0, float a1) {
    int gt = blockIdx.x * 256 + threadIdx.x;
    int x  = gt >> 14;
    const float4* B = reinterpret_cast<const float4*>(g_fB);
    float4 c = B[gt];
    float4 m = B[(x == 0)   ? gt + 255*16384 : gt - 16384];
    float4 p = B[(x == 255) ? gt - 255*16384 : gt + 16384];
    float4 o;
    o.x = fmaf(a1, m.x + p.x, a0 * c.x);
    o.y = fmaf(a1, m.y + p.y, a0 * c.y);
    o.z = fmaf(a1, m.z + p.z, a0 * c.z);
    o.w = fmaf(a1, m.w + p.w, a0 * c.w);
    reinterpret_cast<float4*>(out)[gt] = o;
}

extern "C" void kernel_launch(void* const* d_in, const int* in_sizes, int n_in,
                              void* d_out, int out_size) {
    const float* xyz = (const float*)d_in[0];
    const float* vdw = (const float*)d_in[1];
    int n_atoms = in_sizes[1];
    float* out = (float*)d_out;

    // Gaussian weights in double (matches numpy f64 kernel build), cast to f32.
    double sigma = 1.1 / (100.0 / 256.0) / 4.0;
    double w = exp(-1.0 / (2.0 * sigma * sigma));
    double s = 1.0 + 2.0 * w;
    float a0 = (float)(1.0 / s);
    float a1 = (float)(w / s);

    zero_kernel    <<<(NW/2 + 255) / 256, 256>>>();
    splat_kernel   <<<n_atoms, 128>>>(xyz, vdw, n_atoms);
    classify_kernel<<<256, 256>>>();
    blur_z_kernel  <<<16384, 256>>>(a0, a1);
    blur_y_kernel  <<<16384, 256>>>(a0, a1);
    blur_x_kernel  <<<16384, 256>>>(out, a0, a1);
}